// round 1
// baseline (speedup 1.0000x reference)
#include <cuda_runtime.h>
#include <cstdint>

#define N_NODES 20000
#define KN      32
#define CIN     512
#define COUT    512

#define BM 128
#define BN 128
#define BK 32
#define LDSS 36                 // row stride in floats (+4 pad, keeps 16B align)
#define NKT ((2 * CIN) / BK)    // 32 k-tiles over concatenated K=1024

// scratch for mean-aggregated neighbors (no cudaMalloc allowed)
__device__ float g_agg[(size_t)N_NODES * CIN];

// ---------------------------------------------------------------------------
// Kernel 1: agg[n,c] = mean_k neigh[n,k,c]   (memory-bound)
// ---------------------------------------------------------------------------
__global__ void __launch_bounds__(128) agg_kernel(const float* __restrict__ neigh) {
    const int n  = blockIdx.x;
    const int c4 = threadIdx.x;                         // 0..127 (float4 lanes)
    const float4* base = reinterpret_cast<const float4*>(neigh)
                         + (size_t)n * (KN * CIN / 4) + c4;
    float sx = 0.f, sy = 0.f, sz = 0.f, sw = 0.f;
#pragma unroll 8
    for (int k = 0; k < KN; k++) {
        float4 v = __ldg(&base[(size_t)k * (CIN / 4)]);
        sx += v.x; sy += v.y; sz += v.z; sw += v.w;
    }
    const float inv = 1.0f / (float)KN;
    float4 r = make_float4(sx * inv, sy * inv, sz * inv, sw * inv);
    reinterpret_cast<float4*>(g_agg)[(size_t)n * (CIN / 4) + c4] = r;
}

// ---------------------------------------------------------------------------
// Kernel 2: out[n,o] = sum_c x[n,c]*Wl[o,c] + agg[n,c]*Wr[o,c] + bl[o] + br[o]
// tf32 mma.sync, double-buffered cp.async
// ---------------------------------------------------------------------------
__device__ __forceinline__ uint32_t f2tf32(float f) {
    uint32_t r;
    asm("cvt.rna.tf32.f32 %0, %1;" : "=r"(r) : "f"(f));
    return r;
}

__device__ __forceinline__ void cp_async16(void* s, const void* g) {
    uint32_t sa = (uint32_t)__cvta_generic_to_shared(s);
    asm volatile("cp.async.cg.shared.global [%0], [%1], 16;" :: "r"(sa), "l"(g));
}

__device__ __forceinline__ void cp_commit() {
    asm volatile("cp.async.commit_group;");
}

template <int NW>
__device__ __forceinline__ void cp_wait() {
    asm volatile("cp.async.wait_group %0;" :: "n"(NW));
}

__device__ __forceinline__ void mma_tf32(float c[4], const uint32_t a[4],
                                         uint32_t b0, uint32_t b1) {
    asm volatile(
        "mma.sync.aligned.m16n8k8.row.col.f32.tf32.tf32.f32 "
        "{%0,%1,%2,%3}, {%4,%5,%6,%7}, {%8,%9}, {%0,%1,%2,%3};\n"
        : "+f"(c[0]), "+f"(c[1]), "+f"(c[2]), "+f"(c[3])
        : "r"(a[0]), "r"(a[1]), "r"(a[2]), "r"(a[3]), "r"(b0), "r"(b1));
}

__global__ void __launch_bounds__(256, 2) gemm_kernel(
    const float* __restrict__ x,
    const float* __restrict__ Wl, const float* __restrict__ bl,
    const float* __restrict__ Wr, const float* __restrict__ br,
    float* __restrict__ out)
{
    extern __shared__ float smem[];
    float* As = smem;                       // [2][BM][LDSS]
    float* Bs = smem + 2 * BM * LDSS;       // [2][BN][LDSS]

    const int tid  = threadIdx.x;
    const int warp = tid >> 5;
    const int lane = tid & 31;
    const int gID  = lane >> 2;             // 0..7
    const int tig  = lane & 3;              // 0..3
    const int m0 = blockIdx.x * BM;
    const int n0 = blockIdx.y * BN;
    const int warpM = (warp & 3) * 32;      // 4 warp-rows
    const int warpN = (warp >> 2) * 64;     // 2 warp-cols

    float acc[2][8][4];
#pragma unroll
    for (int i = 0; i < 2; i++)
#pragma unroll
        for (int j = 0; j < 8; j++)
#pragma unroll
            for (int k = 0; k < 4; k++) acc[i][j][k] = 0.f;

    auto issue_tile = [&](int kt, int buf) {
        const int  kbase = kt * BK;
        const bool fromX = (kbase < CIN);
        const float* Aarr = fromX ? x : g_agg;
        const float* Warr = fromX ? Wl : Wr;
        const int kk = fromX ? kbase : (kbase - CIN);
#pragma unroll
        for (int i = 0; i < 4; i++) {
            int idx = tid + i * 256;            // 0..1023
            int r   = idx >> 3;                 // 0..127
            int c4  = idx & 7;                  // 0..7 -> 4-float chunk
            int an = m0 + r;
            if (an > N_NODES - 1) an = N_NODES - 1;   // clamp (store-guarded)
            cp_async16(As + (size_t)buf * BM * LDSS + r * LDSS + c4 * 4,
                       Aarr + (size_t)an * CIN + kk + c4 * 4);
            cp_async16(Bs + (size_t)buf * BN * LDSS + r * LDSS + c4 * 4,
                       Warr + (size_t)(n0 + r) * CIN + kk + c4 * 4);
        }
        cp_commit();
    };

    auto compute_tile = [&](int buf) {
        const float* A = As + (size_t)buf * BM * LDSS;
        const float* B = Bs + (size_t)buf * BN * LDSS;
#pragma unroll
        for (int ks = 0; ks < 4; ks++) {
            const int k0 = ks * 8 + tig;
            uint32_t a[2][4];
#pragma unroll
            for (int mf = 0; mf < 2; mf++) {
                const int r = warpM + mf * 16 + gID;
                a[mf][0] = f2tf32(A[r * LDSS + k0]);
                a[mf][1] = f2tf32(A[(r + 8) * LDSS + k0]);
                a[mf][2] = f2tf32(A[r * LDSS + k0 + 4]);
                a[mf][3] = f2tf32(A[(r + 8) * LDSS + k0 + 4]);
            }
#pragma unroll
            for (int nf = 0; nf < 8; nf++) {
                const int c = warpN + nf * 8 + gID;
                uint32_t b0 = f2tf32(B[c * LDSS + k0]);
                uint32_t b1 = f2tf32(B[c * LDSS + k0 + 4]);
#pragma unroll
                for (int mf = 0; mf < 2; mf++)
                    mma_tf32(acc[mf][nf], a[mf], b0, b1);
            }
        }
    };

    issue_tile(0, 0);
    for (int kt = 0; kt < NKT; kt++) {
        const int cur = kt & 1;
        if (kt + 1 < NKT) {
            issue_tile(kt + 1, cur ^ 1);
            cp_wait<1>();
        } else {
            cp_wait<0>();
        }
        __syncthreads();
        compute_tile(cur);
        __syncthreads();
    }

    // epilogue: add combined bias, guarded fp32 stores (float2)
#pragma unroll
    for (int mf = 0; mf < 2; mf++) {
#pragma unroll
        for (int nf = 0; nf < 8; nf++) {
            const int col = n0 + warpN + nf * 8 + 2 * tig;
            const float bias0 = __ldg(&bl[col]) + __ldg(&br[col]);
            const float bias1 = __ldg(&bl[col + 1]) + __ldg(&br[col + 1]);
            const int row0 = m0 + warpM + mf * 16 + gID;
            if (row0 < N_NODES) {
                float2 v = make_float2(acc[mf][nf][0] + bias0, acc[mf][nf][1] + bias1);
                *reinterpret_cast<float2*>(&out[(size_t)row0 * COUT + col]) = v;
            }
            const int row1 = row0 + 8;
            if (row1 < N_NODES) {
                float2 v = make_float2(acc[mf][nf][2] + bias0, acc[mf][nf][3] + bias1);
                *reinterpret_cast<float2*>(&out[(size_t)row1 * COUT + col]) = v;
            }
        }
    }
}

// ---------------------------------------------------------------------------
extern "C" void kernel_launch(void* const* d_in, const int* in_sizes, int n_in,
                              void* d_out, int out_size) {
    const float* x  = (const float*)d_in[0];
    const float* nx = (const float*)d_in[1];
    const float* Wl = (const float*)d_in[2];
    const float* bl = (const float*)d_in[3];
    const float* Wr = (const float*)d_in[4];
    const float* br = (const float*)d_in[5];
    float* out = (float*)d_out;

    agg_kernel<<<N_NODES, 128>>>(nx);

    const int smem_bytes = 2 * (BM + BN) * LDSS * sizeof(float);  // 73728
    cudaFuncSetAttribute(gemm_kernel,
                         cudaFuncAttributeMaxDynamicSharedMemorySize, smem_bytes);
    dim3 grid((N_NODES + BM - 1) / BM, COUT / BN);
    gemm_kernel<<<grid, 256, smem_bytes>>>(x, Wl, bl, Wr, br, out);
}